// round 10
// baseline (speedup 1.0000x reference)
#include <cuda_runtime.h>
#include <cuda_bf16.h>
#include <math.h>
#include <stdint.h>

#define HDIM   512
#define LWN    32
#define VOCABC 5000
#define MAXLVL 20002
#define MAXCTAS 1024
#define NTOTC  40000
#define NPARC  20000

// smem: 3 stages of [Ah 128x80 | Al 128x80 | Bh 64x80 | Bl 64x80] + rid
#define STAGE   30720
#define A_L_OFF 10240
#define B_H_OFF 20480
#define B_L_OFF 25600
#define RID_OFF 92160
#define SMEM_REQ (92160 + 512)

// ---------------- static device scratch ----------------
__device__ float g_Et[(size_t)VOCABC * HDIM];
__device__ float g_node_h[(size_t)NTOTC * HDIM];
__device__ float g_Wx[(size_t)NPARC * 3 * HDIM];
__device__ float g_mem[(size_t)NPARC * HDIM];
__device__ float g_zbuf[(size_t)NPARC * HDIM];
__device__ __nv_bfloat16 g_xeh[(size_t)NPARC * HDIM];
__device__ __nv_bfloat16 g_xel[(size_t)NPARC * HDIM];
__device__ __nv_bfloat16 g_memh[(size_t)NPARC * HDIM];
__device__ __nv_bfloat16 g_meml[(size_t)NPARC * HDIM];
__device__ __nv_bfloat16 g_mrh[(size_t)NPARC * HDIM];
__device__ __nv_bfloat16 g_mrl[(size_t)NPARC * HDIM];
__device__ __nv_bfloat16 g_Wbh[(size_t)1536 * HDIM];
__device__ __nv_bfloat16 g_Wbl[(size_t)1536 * HDIM];
__device__ __nv_bfloat16 g_Uzh[(size_t)1024 * HDIM];
__device__ __nv_bfloat16 g_Uzl[(size_t)1024 * HDIM];
__device__ __nv_bfloat16 g_Uhh[(size_t)512 * HDIM];
__device__ __nv_bfloat16 g_Uhl[(size_t)512 * HDIM];
__device__ float g_bcat[1536];
__device__ int   g_lvl[NTOTC];
__device__ int   g_order[NPARC];
__device__ int   g_lvl_cnt[MAXLVL];
__device__ int   g_lvl_off[MAXLVL + 2];
__device__ int   g_lvl_cur[MAXLVL];
__device__ int   g_maxlvl;
__device__ float g_part[(size_t)MAXCTAS * HDIM];
__device__ unsigned g_bar_cnt1[64 * 32];
__device__ unsigned g_bar_cnt2;
__device__ unsigned g_bar_gen;

// ---------------- two-level grid barrier ----------------
__device__ __forceinline__ void gbar() {
    __syncthreads();
    if (threadIdx.x == 0) {
        __threadfence();
        const unsigned gen = *((volatile unsigned*)&g_bar_gen);
        const int grp  = blockIdx.x >> 4;
        const int ngrp = ((int)gridDim.x + 15) >> 4;
        const int gsz  = min(16, (int)gridDim.x - (grp << 4));
        if (atomicAdd(&g_bar_cnt1[grp * 32], 1u) == (unsigned)(gsz - 1)) {
            g_bar_cnt1[grp * 32] = 0;
            if (atomicAdd(&g_bar_cnt2, 1u) == (unsigned)(ngrp - 1)) {
                g_bar_cnt2 = 0;
                __threadfence();
                *((volatile unsigned*)&g_bar_gen) = gen + 1u;
            }
        }
        while (*((volatile unsigned*)&g_bar_gen) == gen) { __nanosleep(16); }
        __threadfence();
    }
    __syncthreads();
}

__device__ __forceinline__ float sigm(float x) { return 1.f / (1.f + __expf(-x)); }

// ---------------- PTX helpers ----------------
__device__ __forceinline__ uint32_t s2u(const void* p) {
    uint32_t a;
    asm("{ .reg .u64 t; cvta.to.shared.u64 t, %1; cvt.u32.u64 %0, t; }" : "=r"(a) : "l"(p));
    return a;
}
__device__ __forceinline__ void ldmx4(uint32_t* r, uint32_t addr) {
    asm volatile("ldmatrix.sync.aligned.m8n8.x4.shared.b16 {%0,%1,%2,%3}, [%4];"
        : "=r"(r[0]), "=r"(r[1]), "=r"(r[2]), "=r"(r[3]) : "r"(addr));
}
__device__ __forceinline__ void ldmx2(uint32_t* r, uint32_t addr) {
    asm volatile("ldmatrix.sync.aligned.m8n8.x2.shared.b16 {%0,%1}, [%2];"
        : "=r"(r[0]), "=r"(r[1]) : "r"(addr));
}
__device__ __forceinline__ void hmma(float* d, const uint32_t* a, const uint32_t* b) {
    asm volatile("mma.sync.aligned.m16n8k16.row.col.f32.bf16.bf16.f32 "
        "{%0,%1,%2,%3}, {%4,%5,%6,%7}, {%8,%9}, {%0,%1,%2,%3};"
        : "+f"(d[0]), "+f"(d[1]), "+f"(d[2]), "+f"(d[3])
        : "r"(a[0]), "r"(a[1]), "r"(a[2]), "r"(a[3]), "r"(b[0]), "r"(b[1]));
}
__device__ __forceinline__ void cpa16(uint32_t dst, const __nv_bfloat16* src) {
    asm volatile("cp.async.cg.shared.global [%0], [%1], 16;"
                 :: "r"(dst), "l"(__cvta_generic_to_global(src)));
}
__device__ __forceinline__ void cpa_commit() {
    asm volatile("cp.async.commit_group;" ::: "memory");
}
__device__ __forceinline__ void cpa_wait1() {
    asm volatile("cp.async.wait_group 1;" ::: "memory");
}
__device__ __forceinline__ void cpa_wait0() {
    asm volatile("cp.async.wait_group 0;" ::: "memory");
}
__device__ __forceinline__ void bsplit(float x, __nv_bfloat16* h, __nv_bfloat16* l) {
    __nv_bfloat16 hh = __float2bfloat16(x);
    *h = hh;
    *l = __float2bfloat16(x - __bfloat162float(hh));
}

// ---------------- bf16-split tensor GEMM (3-stage cp.async ring) ----------------
// D[M,Nn] = A[M,512] @ B[Nn,512]^T, A=Ah+Al, B=Bh+Bl (drop Al*Bl).
// MODE 0: g_Wx = D + bcat   MODE 1: z/r gates, mr=r*mem   MODE 2: GRU -> node_h
template<int MODE>
__device__ void tgemm(char* smem, uint32_t sb, int M, const int* __restrict__ rowids,
                      const __nv_bfloat16* __restrict__ Ah, const __nv_bfloat16* __restrict__ Al,
                      const __nv_bfloat16* __restrict__ Bh, const __nv_bfloat16* __restrict__ Bl,
                      int Nn, int L, int cta, int ncta)
{
    const int tid = threadIdx.x;
    const int lane = tid & 31, wid = tid >> 5;
    const int wm = wid & 3, wn = wid >> 2;          // 4x2 warp grid
    int* rid = (int*)(smem + RID_OFF);
    const int nMt = (M + 127) >> 7, nNt = Nn >> 6;
    const int nTiles = nMt * nNt;

    const int arow = tid >> 1, ahalf = tid & 1;
    const int brow = tid >> 2, bseg = tid & 3;

    const uint32_t aLM = (uint32_t)((wm * 32 + (lane & 15)) * 80 + (lane >> 4) * 16);
    const uint32_t bLM = (uint32_t)(B_H_OFF + (wn * 32 + (lane & 7)) * 80 + ((lane >> 3) & 1) * 16);

    for (int tile = cta; tile < nTiles; tile += ncta) {
        const int mt = tile / nNt, nt = tile - mt * nNt;
        const int m0 = mt << 7, n0 = nt << 6;
        __syncthreads();
        if (tid < 128) {
            int rr = m0 + tid;
            rid[tid] = (rr < M) ? (rowids ? rowids[rr] : rr) : -1;
        }
        __syncthreads();

        const int ap = rid[arow];
        const __nv_bfloat16* aph = Ah + (size_t)(ap < 0 ? 0 : ap) * HDIM + ahalf * 16;
        const __nv_bfloat16* apl = Al + (size_t)(ap < 0 ? 0 : ap) * HDIM + ahalf * 16;
        const __nv_bfloat16* bph = Bh + (size_t)(n0 + brow) * HDIM + bseg * 8;
        const __nv_bfloat16* bpl = Bl + (size_t)(n0 + brow) * HDIM + bseg * 8;
        const uint32_t adst = sb + arow * 80 + ahalf * 32;
        const uint32_t bdst = sb + brow * 80 + bseg * 16;

        float acc[2][4][4];
#pragma unroll
        for (int i = 0; i < 2; i++)
#pragma unroll
            for (int j = 0; j < 4; j++)
#pragma unroll
                for (int e = 0; e < 4; e++) acc[i][j][e] = 0.f;

        // prologue: issue chunks 0,1
#pragma unroll
        for (int pc = 0; pc < 2; pc++) {
            const int ke = pc * 32;
            const uint32_t so = (uint32_t)pc * STAGE;
            cpa16(adst + so, aph + ke); cpa16(adst + so + 16, aph + ke + 8);
            cpa16(adst + so + A_L_OFF, apl + ke);
            cpa16(adst + so + A_L_OFF + 16, apl + ke + 8);
            cpa16(bdst + so + B_H_OFF, bph + ke);
            cpa16(bdst + so + B_L_OFF, bpl + ke);
            cpa_commit();
        }
        cpa_wait1();      // chunk 0 landed (this thread)
        __syncthreads();  // chunk 0 landed (all threads)

#pragma unroll 1
        for (int kc = 0; kc < 16; kc++) {
            const uint32_t sbase = sb + (uint32_t)(kc % 3) * STAGE;
            // compute chunk kc
#pragma unroll
            for (int ks = 0; ks < 2; ks++) {
                uint32_t ahf[2][4], alf[2][4], bhf[4][2], blf[4][2];
#pragma unroll
                for (int tm = 0; tm < 2; tm++) {
                    uint32_t aa = sbase + aLM + tm * (16 * 80) + ks * 32;
                    ldmx4(ahf[tm], aa);
                    ldmx4(alf[tm], aa + A_L_OFF);
                }
#pragma unroll
                for (int tn = 0; tn < 4; tn++) {
                    uint32_t ba = sbase + bLM + tn * (8 * 80) + ks * 32;
                    ldmx2(bhf[tn], ba);
                    ldmx2(blf[tn], ba + (B_L_OFF - B_H_OFF));
                }
#pragma unroll
                for (int tm = 0; tm < 2; tm++)
#pragma unroll
                    for (int tn = 0; tn < 4; tn++) {
                        hmma(acc[tm][tn], ahf[tm], bhf[tn]);
                        hmma(acc[tm][tn], ahf[tm], blf[tn]);
                        hmma(acc[tm][tn], alf[tm], bhf[tn]);
                    }
            }
            // issue chunk kc+2 into stage (kc+2)%3 (drained: read in iter kc-1, synced)
            if (kc + 2 < 16) {
                const int ke = (kc + 2) * 32;
                const uint32_t so = (uint32_t)((kc + 2) % 3) * STAGE;
                cpa16(adst + so, aph + ke); cpa16(adst + so + 16, aph + ke + 8);
                cpa16(adst + so + A_L_OFF, apl + ke);
                cpa16(adst + so + A_L_OFF + 16, apl + ke + 8);
                cpa16(bdst + so + B_H_OFF, bph + ke);
                cpa16(bdst + so + B_L_OFF, bpl + ke);
                cpa_commit();
                cpa_wait1();   // chunk kc+1 landed (this thread)
            } else {
                cpa_wait0();
            }
            __syncthreads();   // all read stage kc%3; all have chunk kc+1
        }

        // epilogue
#pragma unroll
        for (int tm = 0; tm < 2; tm++)
#pragma unroll
            for (int e = 0; e < 4; e += 2) {
                const int m = wm * 32 + tm * 16 + (lane >> 2) + ((e >= 2) ? 8 : 0);
                const int p = rid[m];
                if (p < 0) continue;
#pragma unroll
                for (int tn = 0; tn < 4; tn++)
#pragma unroll
                    for (int u = 0; u < 2; u++) {
                        const int c = n0 + wn * 32 + tn * 8 + (lane & 3) * 2 + u;
                        const float v = acc[tm][tn][e + u];
                        if (MODE == 0) {
                            g_Wx[(size_t)p * 1536 + c] = v + g_bcat[c];
                        } else if (MODE == 1) {
                            if (c < 512) {
                                g_zbuf[(size_t)p * HDIM + c] =
                                    sigm(v + g_Wx[(size_t)p * 1536 + c]);
                            } else {
                                const int c2 = c - 512;
                                float r = sigm(v + g_Wx[(size_t)p * 1536 + 512 + c2]);
                                float mr = r * g_mem[(size_t)p * HDIM + c2];
                                bsplit(mr, &g_mrh[(size_t)p * HDIM + c2],
                                           &g_mrl[(size_t)p * HDIM + c2]);
                            }
                        } else {
                            float cc = tanhf(v + g_Wx[(size_t)p * 1536 + 1024 + c]);
                            float z  = g_zbuf[(size_t)p * HDIM + c];
                            float mm = g_mem[(size_t)p * HDIM + c];
                            g_node_h[(size_t)(L + p) * HDIM + c] = z * mm + (1.f - z) * cc;
                        }
                    }
            }
    }
}

// ---------------- 5-layer star attention, one warp per (parent, half) ----------------
__device__ void attn_phase(int off, int B, const int* __restrict__ tree)
{
    const int lane = threadIdx.x & 31;
    const int gw = (blockIdx.x * blockDim.x + threadIdx.x) >> 5;
    const int nw = (gridDim.x * blockDim.x) >> 5;
    for (int item = gw; item < 2 * B; item += nw) {
        const int p = g_order[off + (item >> 1)];
        const int half = item & 1;
        const int cbase = half * 256 + lane * 8;
        float v[4][8];
        unsigned mb = 0u;
#pragma unroll
        for (int i = 0; i < 4; i++) {
            int c = tree[p * 4 + i];
            if (c >= 0) {
                mb |= (1u << i);
                const float4* hp = (const float4*)(g_node_h + (size_t)c * HDIM + cbase);
                float4 a = hp[0], b = hp[1];
                v[i][0]=a.x; v[i][1]=a.y; v[i][2]=a.z; v[i][3]=a.w;
                v[i][4]=b.x; v[i][5]=b.y; v[i][6]=b.z; v[i][7]=b.w;
            } else {
#pragma unroll
                for (int j = 0; j < 8; j++) v[i][j] = 0.f;
            }
        }
        const float denom = (float)max(__popc(mb), 1);
#pragma unroll 1
        for (int layer = 0; layer < 5; layer++) {
            float s[4][4];
#pragma unroll
            for (int i = 0; i < 4; i++)
#pragma unroll
                for (int k = 0; k < 4; k++) {
                    float t = 0.f;
#pragma unroll
                    for (int j = 0; j < 8; j++) t += v[i][j] * v[k][j];
                    t += __shfl_xor_sync(0xffffffffu, t, 1);
                    t += __shfl_xor_sync(0xffffffffu, t, 2);
                    t += __shfl_xor_sync(0xffffffffu, t, 4);
                    s[i][k] = ((mb >> k) & 1u) ? t * 0.125f : -1e9f;
                }
#pragma unroll
            for (int i = 0; i < 4; i++) {
                float mx = fmaxf(fmaxf(s[i][0], s[i][1]), fmaxf(s[i][2], s[i][3]));
                float e0 = __expf(s[i][0]-mx), e1 = __expf(s[i][1]-mx);
                float e2 = __expf(s[i][2]-mx), e3 = __expf(s[i][3]-mx);
                float inv = 1.f / (e0+e1+e2+e3);
                s[i][0]=e0*inv; s[i][1]=e1*inv; s[i][2]=e2*inv; s[i][3]=e3*inv;
            }
            float o[4][8];
#pragma unroll
            for (int i = 0; i < 4; i++)
#pragma unroll
                for (int j = 0; j < 8; j++)
                    o[i][j] = s[i][0]*v[0][j] + s[i][1]*v[1][j]
                            + s[i][2]*v[2][j] + s[i][3]*v[3][j];
#pragma unroll
            for (int i = 0; i < 4; i++)
#pragma unroll
                for (int j = 0; j < 8; j++) v[i][j] = o[i][j];
        }
        float m8[8];
#pragma unroll
        for (int j = 0; j < 8; j++) {
            float t = 0.f;
#pragma unroll
            for (int i = 0; i < 4; i++) if ((mb >> i) & 1u) t += v[i][j];
            m8[j] = t / denom;
        }
        float4* mp = (float4*)(g_mem + (size_t)p * HDIM + cbase);
        mp[0] = make_float4(m8[0], m8[1], m8[2], m8[3]);
        mp[1] = make_float4(m8[4], m8[5], m8[6], m8[7]);
#pragma unroll
        for (int j = 0; j < 8; j++)
            bsplit(m8[j], &g_memh[(size_t)p * HDIM + cbase + j],
                          &g_meml[(size_t)p * HDIM + cbase + j]);
    }
}

// embed one node per CTA iteration (256 threads, 2 cols each)
__device__ __forceinline__ void embed_node(int n, int L,
    const float* __restrict__ xw, const int* __restrict__ xi)
{
    const int tid = threadIdx.x;
    const int c0 = tid, c1 = tid + 256;
    const int4*   ip4 = (const int4*)(xi + (size_t)n * LWN);
    const float4* wp4 = (const float4*)(xw + (size_t)n * LWN);
    float a0 = 0.f, a1 = 0.f;
#pragma unroll
    for (int q = 0; q < 8; q++) {
        int4 iv = ip4[q]; float4 wv = wp4[q];
        const float* e0 = g_Et + (size_t)iv.x * HDIM;
        const float* e1 = g_Et + (size_t)iv.y * HDIM;
        const float* e2 = g_Et + (size_t)iv.z * HDIM;
        const float* e3 = g_Et + (size_t)iv.w * HDIM;
        a0 += e0[c0]*wv.x + e1[c0]*wv.y + e2[c0]*wv.z + e3[c0]*wv.w;
        a1 += e0[c1]*wv.x + e1[c1]*wv.y + e2[c1]*wv.z + e3[c1]*wv.w;
    }
    if (n < L) {
        g_node_h[(size_t)n * HDIM + c0] = a0;
        g_node_h[(size_t)n * HDIM + c1] = a1;
    } else {
        const size_t pp = (size_t)(n - L) * HDIM;
        bsplit(a0, &g_xeh[pp + c0], &g_xel[pp + c0]);
        bsplit(a1, &g_xeh[pp + c1], &g_xel[pp + c1]);
    }
}

// ---------------- the persistent kernel ----------------
extern "C" __global__ void __launch_bounds__(256, 2) star_all(
    const float* __restrict__ xw, const int* __restrict__ xi, const int* __restrict__ tree,
    const float* __restrict__ Ebu,
    const float* __restrict__ Wz, const float* __restrict__ Uz, const float* __restrict__ bz,
    const float* __restrict__ Wr, const float* __restrict__ Ur, const float* __restrict__ br,
    const float* __restrict__ Wh, const float* __restrict__ Uh, const float* __restrict__ bh,
    const float* __restrict__ Wout, const float* __restrict__ bout,
    float* __restrict__ out, int N, int P)
{
    extern __shared__ char smem[];
    const uint32_t sb = s2u(smem);

    const int L = N - P;
    const int tid = threadIdx.x;
    const int gtid = blockIdx.x * blockDim.x + tid;
    const int nthreads = gridDim.x * blockDim.x;

    // ---- P0: init + weight bf16 split + tiled transpose of E ----
    for (int n = gtid; n < N; n += nthreads) g_lvl[n] = (n < L) ? 0 : -1;
    for (int i = gtid; i < MAXLVL; i += nthreads) g_lvl_cnt[i] = 0;
    if (gtid == 0) g_maxlvl = 0;
    for (int e = gtid; e < 1536 * HDIM; e += nthreads) {
        int r = e >> 9, c = e & 511;
        float w = (r < 512) ? Wz[r * 512 + c] : (r < 1024) ? Wr[(r - 512) * 512 + c]
                                              : Wh[(r - 1024) * 512 + c];
        bsplit(w, &g_Wbh[e], &g_Wbl[e]);
    }
    for (int e = gtid; e < 1024 * HDIM; e += nthreads) {
        int r = e >> 9, c = e & 511;
        float w = (r < 512) ? Uz[r * 512 + c] : Ur[(r - 512) * 512 + c];
        bsplit(w, &g_Uzh[e], &g_Uzl[e]);
    }
    for (int e = gtid; e < 512 * HDIM; e += nthreads)
        bsplit(Uh[e], &g_Uhh[e], &g_Uhl[e]);
    for (int i = gtid; i < 1536; i += nthreads)
        g_bcat[i] = (i < 512) ? bz[i] : (i < 1024) ? br[i - 512] : bh[i - 1024];
    // tiled transpose: g_Et[v][h] = Ebu[h][v], coalesced both sides
    {
        float (*tp)[33] = (float(*)[33])smem;
        const int nvt = (VOCABC + 31) >> 5;          // 157
        const int nht = HDIM >> 5;                   // 16
        const int tx = tid & 31, ty = tid >> 5;      // 8 rows per pass
        for (int t = blockIdx.x; t < nvt * nht; t += gridDim.x) {
            const int vt = t / nht, ht = t - vt * nht;
            const int v0 = vt << 5, h0 = ht << 5;
            __syncthreads();
#pragma unroll
            for (int i = 0; i < 4; i++) {
                int r = ty + i * 8;                   // h offset
                int v = v0 + tx;
                if (v < VOCABC) tp[r][tx] = Ebu[(size_t)(h0 + r) * VOCABC + v];
            }
            __syncthreads();
#pragma unroll
            for (int i = 0; i < 4; i++) {
                int r = ty + i * 8;                   // v offset
                int v = v0 + r;
                if (v < VOCABC) g_Et[(size_t)v * HDIM + h0 + tx] = tp[tx][r];
            }
        }
        __syncthreads();
    }
    gbar();

    // ---- P1: parent embedding + level discovery ----
    for (int n = L + blockIdx.x; n < N; n += gridDim.x) embed_node(n, L, xw, xi);
    for (int p = gtid; p < P; p += nthreads) {
        int lv = 0;
#pragma unroll
        for (int i = 0; i < 4; i++) {
            int c = tree[p * 4 + i];
            if (c >= 0) {
                int cl;
                if (c < L) cl = 0;
                else { while ((cl = *((volatile int*)&g_lvl[c])) < 0) { __nanosleep(32); } }
                lv = max(lv, cl);
            }
        }
        lv += 1;
        *((volatile int*)&g_lvl[L + p]) = lv;
        atomicAdd(&g_lvl_cnt[lv], 1);
        atomicMax(&g_maxlvl, lv);
    }
    gbar();

    // ---- P2: leaf embedding (blocks < E) || Wx GEMM (blocks >= E); block0 tid0 prefix ----
    {
        const int E = min(120, (int)gridDim.x >> 1);
        if (blockIdx.x == 0 && tid == 0) {
            int ml = g_maxlvl;
            int run = 0;
            for (int lv = 1; lv <= ml; lv++) {
                g_lvl_off[lv] = run;
                g_lvl_cur[lv] = run;
                run += g_lvl_cnt[lv];
            }
            g_lvl_off[ml + 1] = run;
        }
        if ((int)blockIdx.x < E) {
            __syncthreads();
            for (int n = blockIdx.x; n < L; n += E) embed_node(n, L, xw, xi);
        } else {
            tgemm<0>(smem, sb, P, nullptr, g_xeh, g_xel, g_Wbh, g_Wbl,
                     1536, L, blockIdx.x - E, gridDim.x - E);
        }
    }
    gbar();

    // ---- P3: scatter parents into level order ----
    for (int p = gtid; p < P; p += nthreads) {
        int lv = g_lvl[L + p];
        int slot = atomicAdd(&g_lvl_cur[lv], 1);
        g_order[slot] = p;
    }
    gbar();

    // ---- level loop ----
    const int maxlvl = g_maxlvl;
    for (int lv = 1; lv <= maxlvl; lv++) {
        const int off = g_lvl_off[lv];
        const int cnt = g_lvl_off[lv + 1] - off;
        if (cnt == 0) continue;
        attn_phase(off, cnt, tree);
        gbar();
        tgemm<1>(smem, sb, cnt, g_order + off, g_memh, g_meml,
                 g_Uzh, g_Uzl, 1024, L, blockIdx.x, gridDim.x);
        gbar();
        tgemm<2>(smem, sb, cnt, g_order + off, g_mrh, g_mrl,
                 g_Uhh, g_Uhl, 512, L, blockIdx.x, gridDim.x);
        gbar();
    }

    // ---- P5: per-CTA column max over parents ----
    {
        const int rpc = (P + gridDim.x - 1) / gridDim.x;
        const int r0 = blockIdx.x * rpc;
        const int r1 = min(r0 + rpc, P);
        const int c0 = tid, c1 = tid + 256;
        float v0 = -3.4e38f, v1 = -3.4e38f;
        for (int r = r0; r < r1; r++) {
            const float* row = g_node_h + (size_t)(L + r) * HDIM;
            v0 = fmaxf(v0, row[c0]);
            v1 = fmaxf(v1, row[c1]);
        }
        g_part[(size_t)blockIdx.x * HDIM + c0] = v0;
        g_part[(size_t)blockIdx.x * HDIM + c1] = v1;
    }
    gbar();

    // ---- P6: block 0: reduce, matvec, softmax ----
    if (blockIdx.x == 0) {
        float* sfinal = (float*)smem;
        float* slog   = sfinal + HDIM;
        const int c0 = tid, c1 = tid + 256;
        float v0 = -3.4e38f, v1 = -3.4e38f;
        for (int g = 0; g < (int)gridDim.x; g++) {
            v0 = fmaxf(v0, g_part[(size_t)g * HDIM + c0]);
            v1 = fmaxf(v1, g_part[(size_t)g * HDIM + c1]);
        }
        sfinal[c0] = v0; sfinal[c1] = v1;
        __syncthreads();
        const int w = tid >> 5, lane = tid & 31;
        if (w < 4) {
            float t = 0.f;
#pragma unroll
            for (int j = 0; j < 16; j++) {
                int c = lane * 16 + j;
                t += Wout[w * HDIM + c] * sfinal[c];
            }
#pragma unroll
            for (int d = 16; d > 0; d >>= 1) t += __shfl_xor_sync(0xffffffffu, t, d);
            if (lane == 0) slog[w] = t + bout[w];
        }
        __syncthreads();
        if (tid == 0) {
            float mx = fmaxf(fmaxf(slog[0], slog[1]), fmaxf(slog[2], slog[3]));
            float e0 = __expf(slog[0]-mx), e1 = __expf(slog[1]-mx);
            float e2 = __expf(slog[2]-mx), e3 = __expf(slog[3]-mx);
            float inv = 1.f / (e0+e1+e2+e3);
            out[0] = e0*inv; out[1] = e1*inv; out[2] = e2*inv; out[3] = e3*inv;
        }
    }
}

extern "C" void kernel_launch(void* const* d_in, const int* in_sizes, int n_in,
                              void* d_out, int out_size) {
    const float* xw   = (const float*)d_in[0];
    const int*   xi   = (const int*)  d_in[1];
    const int*   tree = (const int*)  d_in[2];
    const float* Ebu  = (const float*)d_in[3];
    const float* Wz   = (const float*)d_in[4];
    const float* Uz   = (const float*)d_in[5];
    const float* bz   = (const float*)d_in[6];
    const float* Wr   = (const float*)d_in[7];
    const float* Ur   = (const float*)d_in[8];
    const float* br   = (const float*)d_in[9];
    const float* Wh   = (const float*)d_in[10];
    const float* Uh   = (const float*)d_in[11];
    const float* bh   = (const float*)d_in[12];
    const float* Wout = (const float*)d_in[13];
    const float* bout = (const float*)d_in[14];
    float* out = (float*)d_out;

    const int N = in_sizes[0] / LWN;
    const int P = in_sizes[2] / 4;

    int dev = 0;
    cudaGetDevice(&dev);
    int smCount = 148;
    cudaDeviceGetAttribute(&smCount, cudaDevAttrMultiProcessorCount, dev);

    cudaFuncSetAttribute(star_all, cudaFuncAttributeMaxDynamicSharedMemorySize, SMEM_REQ);
    int bpm = 1;
    cudaOccupancyMaxActiveBlocksPerMultiprocessor(&bpm, star_all, 256, SMEM_REQ);
    if (bpm < 1) bpm = 1;
    int grid = smCount * bpm;
    if (grid > MAXCTAS) grid = MAXCTAS;

    star_all<<<grid, 256, SMEM_REQ>>>(xw, xi, tree, Ebu, Wz, Uz, bz, Wr, Ur, br,
                                      Wh, Uh, bh, Wout, bout, out, N, P);
}

// round 11
// speedup vs baseline: 1.1361x; 1.1361x over previous
#include <cuda_runtime.h>
#include <cuda_bf16.h>
#include <math.h>
#include <stdint.h>

#define HDIM   512
#define LWN    32
#define VOCABC 5000
#define MAXLVL 20002
#define MAXCTAS 1024
#define NTOTC  40000
#define NPARC  20000

// smem: 3 stages of [Ah 128x80 | Al 128x80 | Bh 64x80 | Bl 64x80] + rid
#define STAGE   30720
#define A_L_OFF 10240
#define B_H_OFF 20480
#define B_L_OFF 25600
#define RID_OFF 92160
#define SMEM_REQ (92160 + 512)

// ---------------- static device scratch ----------------
__device__ float g_Et[(size_t)VOCABC * HDIM];
__device__ float g_node_h[(size_t)NTOTC * HDIM];
__device__ float g_Wx[(size_t)NPARC * 3 * HDIM];
__device__ float g_mem[(size_t)NPARC * HDIM];
__device__ float g_zbuf[(size_t)NPARC * HDIM];
__device__ __nv_bfloat16 g_xeh[(size_t)NPARC * HDIM];
__device__ __nv_bfloat16 g_xel[(size_t)NPARC * HDIM];
__device__ __nv_bfloat16 g_memh[(size_t)NPARC * HDIM];
__device__ __nv_bfloat16 g_meml[(size_t)NPARC * HDIM];
__device__ __nv_bfloat16 g_mrh[(size_t)NPARC * HDIM];
__device__ __nv_bfloat16 g_mrl[(size_t)NPARC * HDIM];
__device__ __nv_bfloat16 g_Wbh[(size_t)1536 * HDIM];
__device__ __nv_bfloat16 g_Wbl[(size_t)1536 * HDIM];
__device__ __nv_bfloat16 g_Uzh[(size_t)1024 * HDIM];
__device__ __nv_bfloat16 g_Uzl[(size_t)1024 * HDIM];
__device__ __nv_bfloat16 g_Uhh[(size_t)512 * HDIM];
__device__ __nv_bfloat16 g_Uhl[(size_t)512 * HDIM];
__device__ float g_bcat[1536];
__device__ int   g_lvl[NTOTC];
__device__ int   g_order[NPARC];
__device__ int   g_lvl_cnt[MAXLVL];
__device__ int   g_lvl_off[MAXLVL + 2];
__device__ int   g_lvl_cur[MAXLVL];
__device__ int   g_maxlvl;
__device__ float g_part[(size_t)MAXCTAS * HDIM];
__device__ unsigned g_bar_cnt1[64 * 32];
__device__ unsigned g_bar_cnt2;
__device__ unsigned g_bar_gen;

// ---------------- two-level grid barrier ----------------
__device__ __forceinline__ void gbar() {
    __syncthreads();
    if (threadIdx.x == 0) {
        __threadfence();
        const unsigned gen = *((volatile unsigned*)&g_bar_gen);
        const int grp  = blockIdx.x >> 4;
        const int ngrp = ((int)gridDim.x + 15) >> 4;
        const int gsz  = min(16, (int)gridDim.x - (grp << 4));
        if (atomicAdd(&g_bar_cnt1[grp * 32], 1u) == (unsigned)(gsz - 1)) {
            g_bar_cnt1[grp * 32] = 0;
            if (atomicAdd(&g_bar_cnt2, 1u) == (unsigned)(ngrp - 1)) {
                g_bar_cnt2 = 0;
                __threadfence();
                *((volatile unsigned*)&g_bar_gen) = gen + 1u;
            }
        }
        while (*((volatile unsigned*)&g_bar_gen) == gen) { __nanosleep(16); }
        __threadfence();
    }
    __syncthreads();
}

__device__ __forceinline__ float sigm(float x) { return 1.f / (1.f + __expf(-x)); }

// ---------------- PTX helpers ----------------
__device__ __forceinline__ uint32_t s2u(const void* p) {
    uint32_t a;
    asm("{ .reg .u64 t; cvta.to.shared.u64 t, %1; cvt.u32.u64 %0, t; }" : "=r"(a) : "l"(p));
    return a;
}
__device__ __forceinline__ void ldmx4(uint32_t* r, uint32_t addr) {
    asm volatile("ldmatrix.sync.aligned.m8n8.x4.shared.b16 {%0,%1,%2,%3}, [%4];"
        : "=r"(r[0]), "=r"(r[1]), "=r"(r[2]), "=r"(r[3]) : "r"(addr));
}
__device__ __forceinline__ void ldmx2(uint32_t* r, uint32_t addr) {
    asm volatile("ldmatrix.sync.aligned.m8n8.x2.shared.b16 {%0,%1}, [%2];"
        : "=r"(r[0]), "=r"(r[1]) : "r"(addr));
}
__device__ __forceinline__ void hmma(float* d, const uint32_t* a, const uint32_t* b) {
    asm volatile("mma.sync.aligned.m16n8k16.row.col.f32.bf16.bf16.f32 "
        "{%0,%1,%2,%3}, {%4,%5,%6,%7}, {%8,%9}, {%0,%1,%2,%3};"
        : "+f"(d[0]), "+f"(d[1]), "+f"(d[2]), "+f"(d[3])
        : "r"(a[0]), "r"(a[1]), "r"(a[2]), "r"(a[3]), "r"(b[0]), "r"(b[1]));
}
__device__ __forceinline__ void cpa16(uint32_t dst, const __nv_bfloat16* src) {
    asm volatile("cp.async.cg.shared.global [%0], [%1], 16;"
                 :: "r"(dst), "l"(__cvta_generic_to_global(src)));
}
__device__ __forceinline__ void cpa_commit() {
    asm volatile("cp.async.commit_group;" ::: "memory");
}
__device__ __forceinline__ void cpa_wait1() {
    asm volatile("cp.async.wait_group 1;" ::: "memory");
}
__device__ __forceinline__ void cpa_wait0() {
    asm volatile("cp.async.wait_group 0;" ::: "memory");
}
__device__ __forceinline__ void bsplit(float x, __nv_bfloat16* h, __nv_bfloat16* l) {
    __nv_bfloat16 hh = __float2bfloat16(x);
    *h = hh;
    *l = __float2bfloat16(x - __bfloat162float(hh));
}
// pack two floats -> hi bf16x2 (ret) and lo bf16x2 (*lo)
__device__ __forceinline__ uint32_t pack2(float a, float b, uint32_t* lo) {
    __nv_bfloat16 ha = __float2bfloat16(a), hb = __float2bfloat16(b);
    __nv_bfloat16 la = __float2bfloat16(a - __bfloat162float(ha));
    __nv_bfloat16 lb = __float2bfloat16(b - __bfloat162float(hb));
    uint32_t h = (uint32_t)*(uint16_t*)&ha | ((uint32_t)*(uint16_t*)&hb << 16);
    *lo = (uint32_t)*(uint16_t*)&la | ((uint32_t)*(uint16_t*)&lb << 16);
    return h;
}

// ---------------- bf16-split tensor GEMM (3-stage cp.async ring) ----------------
template<int MODE>
__device__ void tgemm(char* smem, uint32_t sb, int M, const int* __restrict__ rowids,
                      const __nv_bfloat16* __restrict__ Ah, const __nv_bfloat16* __restrict__ Al,
                      const __nv_bfloat16* __restrict__ Bh, const __nv_bfloat16* __restrict__ Bl,
                      int Nn, int L, int cta, int ncta)
{
    const int tid = threadIdx.x;
    const int lane = tid & 31, wid = tid >> 5;
    const int wm = wid & 3, wn = wid >> 2;
    int* rid = (int*)(smem + RID_OFF);
    const int nMt = (M + 127) >> 7, nNt = Nn >> 6;
    const int nTiles = nMt * nNt;

    const int arow = tid >> 1, ahalf = tid & 1;
    const int brow = tid >> 2, bseg = tid & 3;

    const uint32_t aLM = (uint32_t)((wm * 32 + (lane & 15)) * 80 + (lane >> 4) * 16);
    const uint32_t bLM = (uint32_t)(B_H_OFF + (wn * 32 + (lane & 7)) * 80 + ((lane >> 3) & 1) * 16);

    for (int tile = cta; tile < nTiles; tile += ncta) {
        const int mt = tile / nNt, nt = tile - mt * nNt;
        const int m0 = mt << 7, n0 = nt << 6;
        __syncthreads();
        if (tid < 128) {
            int rr = m0 + tid;
            rid[tid] = (rr < M) ? (rowids ? rowids[rr] : rr) : -1;
        }
        __syncthreads();

        const int ap = rid[arow];
        const __nv_bfloat16* aph = Ah + (size_t)(ap < 0 ? 0 : ap) * HDIM + ahalf * 16;
        const __nv_bfloat16* apl = Al + (size_t)(ap < 0 ? 0 : ap) * HDIM + ahalf * 16;
        const __nv_bfloat16* bph = Bh + (size_t)(n0 + brow) * HDIM + bseg * 8;
        const __nv_bfloat16* bpl = Bl + (size_t)(n0 + brow) * HDIM + bseg * 8;
        const uint32_t adst = sb + arow * 80 + ahalf * 32;
        const uint32_t bdst = sb + brow * 80 + bseg * 16;

        float acc[2][4][4];
#pragma unroll
        for (int i = 0; i < 2; i++)
#pragma unroll
            for (int j = 0; j < 4; j++)
#pragma unroll
                for (int e = 0; e < 4; e++) acc[i][j][e] = 0.f;

#pragma unroll
        for (int pc = 0; pc < 2; pc++) {
            const int ke = pc * 32;
            const uint32_t so = (uint32_t)pc * STAGE;
            cpa16(adst + so, aph + ke); cpa16(adst + so + 16, aph + ke + 8);
            cpa16(adst + so + A_L_OFF, apl + ke);
            cpa16(adst + so + A_L_OFF + 16, apl + ke + 8);
            cpa16(bdst + so + B_H_OFF, bph + ke);
            cpa16(bdst + so + B_L_OFF, bpl + ke);
            cpa_commit();
        }
        cpa_wait1();
        __syncthreads();

#pragma unroll 1
        for (int kc = 0; kc < 16; kc++) {
            const uint32_t sbase = sb + (uint32_t)(kc % 3) * STAGE;
#pragma unroll
            for (int ks = 0; ks < 2; ks++) {
                uint32_t ahf[2][4], alf[2][4], bhf[4][2], blf[4][2];
#pragma unroll
                for (int tm = 0; tm < 2; tm++) {
                    uint32_t aa = sbase + aLM + tm * (16 * 80) + ks * 32;
                    ldmx4(ahf[tm], aa);
                    ldmx4(alf[tm], aa + A_L_OFF);
                }
#pragma unroll
                for (int tn = 0; tn < 4; tn++) {
                    uint32_t ba = sbase + bLM + tn * (8 * 80) + ks * 32;
                    ldmx2(bhf[tn], ba);
                    ldmx2(blf[tn], ba + (B_L_OFF - B_H_OFF));
                }
#pragma unroll
                for (int tm = 0; tm < 2; tm++)
#pragma unroll
                    for (int tn = 0; tn < 4; tn++) {
                        hmma(acc[tm][tn], ahf[tm], bhf[tn]);
                        hmma(acc[tm][tn], ahf[tm], blf[tn]);
                        hmma(acc[tm][tn], alf[tm], bhf[tn]);
                    }
            }
            if (kc + 2 < 16) {
                const int ke = (kc + 2) * 32;
                const uint32_t so = (uint32_t)((kc + 2) % 3) * STAGE;
                cpa16(adst + so, aph + ke); cpa16(adst + so + 16, aph + ke + 8);
                cpa16(adst + so + A_L_OFF, apl + ke);
                cpa16(adst + so + A_L_OFF + 16, apl + ke + 8);
                cpa16(bdst + so + B_H_OFF, bph + ke);
                cpa16(bdst + so + B_L_OFF, bpl + ke);
                cpa_commit();
                cpa_wait1();
            } else {
                cpa_wait0();
            }
            __syncthreads();
        }

        // epilogue (vectorized stores: each thread owns col pair c, c+1)
#pragma unroll
        for (int tm = 0; tm < 2; tm++)
#pragma unroll
            for (int e = 0; e < 4; e += 2) {
                const int m = wm * 32 + tm * 16 + (lane >> 2) + ((e >= 2) ? 8 : 0);
                const int p = rid[m];
                if (p < 0) continue;
#pragma unroll
                for (int tn = 0; tn < 4; tn++) {
                    const int c = n0 + wn * 32 + tn * 8 + (lane & 3) * 2;
                    const float v0 = acc[tm][tn][e], v1 = acc[tm][tn][e + 1];
                    if (MODE == 0) {
                        *(float2*)&g_Wx[(size_t)p * 1536 + c] =
                            make_float2(v0 + g_bcat[c], v1 + g_bcat[c + 1]);
                    } else if (MODE == 1) {
                        if (c < 512) {
                            float2 wx = *(const float2*)&g_Wx[(size_t)p * 1536 + c];
                            *(float2*)&g_zbuf[(size_t)p * HDIM + c] =
                                make_float2(sigm(v0 + wx.x), sigm(v1 + wx.y));
                        } else {
                            const int c2 = c - 512;
                            float2 wx = *(const float2*)&g_Wx[(size_t)p * 1536 + 512 + c2];
                            float2 mm = *(const float2*)&g_mem[(size_t)p * HDIM + c2];
                            float mr0 = sigm(v0 + wx.x) * mm.x;
                            float mr1 = sigm(v1 + wx.y) * mm.y;
                            uint32_t lo, hi = pack2(mr0, mr1, &lo);
                            *(uint32_t*)&g_mrh[(size_t)p * HDIM + c2] = hi;
                            *(uint32_t*)&g_mrl[(size_t)p * HDIM + c2] = lo;
                        }
                    } else {
                        float2 wx = *(const float2*)&g_Wx[(size_t)p * 1536 + 1024 + c];
                        float2 zz = *(const float2*)&g_zbuf[(size_t)p * HDIM + c];
                        float2 mm = *(const float2*)&g_mem[(size_t)p * HDIM + c];
                        float cc0 = tanhf(v0 + wx.x), cc1 = tanhf(v1 + wx.y);
                        *(float2*)&g_node_h[(size_t)(L + p) * HDIM + c] =
                            make_float2(zz.x * mm.x + (1.f - zz.x) * cc0,
                                        zz.y * mm.y + (1.f - zz.y) * cc1);
                    }
                }
            }
    }
}

// ---------------- 5-layer star attention, one warp per (parent, half) ----------------
__device__ void attn_phase(int off, int B, const int* __restrict__ tree)
{
    const int lane = threadIdx.x & 31;
    const int gw = (blockIdx.x * blockDim.x + threadIdx.x) >> 5;
    const int nw = (gridDim.x * blockDim.x) >> 5;
    for (int item = gw; item < 2 * B; item += nw) {
        const int p = g_order[off + (item >> 1)];
        const int half = item & 1;
        const int cbase = half * 256 + lane * 8;
        float v[4][8];
        unsigned mb = 0u;
#pragma unroll
        for (int i = 0; i < 4; i++) {
            int c = tree[p * 4 + i];
            if (c >= 0) {
                mb |= (1u << i);
                const float4* hp = (const float4*)(g_node_h + (size_t)c * HDIM + cbase);
                float4 a = hp[0], b = hp[1];
                v[i][0]=a.x; v[i][1]=a.y; v[i][2]=a.z; v[i][3]=a.w;
                v[i][4]=b.x; v[i][5]=b.y; v[i][6]=b.z; v[i][7]=b.w;
            } else {
#pragma unroll
                for (int j = 0; j < 8; j++) v[i][j] = 0.f;
            }
        }
        const float denom = (float)max(__popc(mb), 1);
#pragma unroll 1
        for (int layer = 0; layer < 5; layer++) {
            float s[4][4];
#pragma unroll
            for (int i = 0; i < 4; i++)
#pragma unroll
                for (int k = 0; k < 4; k++) {
                    float t = 0.f;
#pragma unroll
                    for (int j = 0; j < 8; j++) t += v[i][j] * v[k][j];
                    t += __shfl_xor_sync(0xffffffffu, t, 1);
                    t += __shfl_xor_sync(0xffffffffu, t, 2);
                    t += __shfl_xor_sync(0xffffffffu, t, 4);
                    s[i][k] = ((mb >> k) & 1u) ? t * 0.125f : -1e9f;
                }
#pragma unroll
            for (int i = 0; i < 4; i++) {
                float mx = fmaxf(fmaxf(s[i][0], s[i][1]), fmaxf(s[i][2], s[i][3]));
                float e0 = __expf(s[i][0]-mx), e1 = __expf(s[i][1]-mx);
                float e2 = __expf(s[i][2]-mx), e3 = __expf(s[i][3]-mx);
                float inv = 1.f / (e0+e1+e2+e3);
                s[i][0]=e0*inv; s[i][1]=e1*inv; s[i][2]=e2*inv; s[i][3]=e3*inv;
            }
            float o[4][8];
#pragma unroll
            for (int i = 0; i < 4; i++)
#pragma unroll
                for (int j = 0; j < 8; j++)
                    o[i][j] = s[i][0]*v[0][j] + s[i][1]*v[1][j]
                            + s[i][2]*v[2][j] + s[i][3]*v[3][j];
#pragma unroll
            for (int i = 0; i < 4; i++)
#pragma unroll
                for (int j = 0; j < 8; j++) v[i][j] = o[i][j];
        }
        float m8[8];
#pragma unroll
        for (int j = 0; j < 8; j++) {
            float t = 0.f;
#pragma unroll
            for (int i = 0; i < 4; i++) if ((mb >> i) & 1u) t += v[i][j];
            m8[j] = t / denom;
        }
        float4* mp = (float4*)(g_mem + (size_t)p * HDIM + cbase);
        mp[0] = make_float4(m8[0], m8[1], m8[2], m8[3]);
        mp[1] = make_float4(m8[4], m8[5], m8[6], m8[7]);
        uint32_t ph[4], pl[4];
#pragma unroll
        for (int j2 = 0; j2 < 4; j2++)
            ph[j2] = pack2(m8[2*j2], m8[2*j2+1], &pl[j2]);
        *(uint4*)&g_memh[(size_t)p * HDIM + cbase] = make_uint4(ph[0], ph[1], ph[2], ph[3]);
        *(uint4*)&g_meml[(size_t)p * HDIM + cbase] = make_uint4(pl[0], pl[1], pl[2], pl[3]);
    }
}

// embed a PAIR of nodes per CTA iteration: thread t -> node n0+(t>>7), cols [(t&127)*4, +4)
__device__ __forceinline__ void embed_pair(int n0, int L, int bound,
    const float* __restrict__ xw, const int* __restrict__ xi)
{
    const int tid = threadIdx.x;
    const int n = n0 + (tid >> 7);
    if (n >= bound) return;
    const int c4 = (tid & 127) << 2;
    const int*   ip = xi + (size_t)n * LWN;
    const float* wp = xw + (size_t)n * LWN;
    float4 acc = make_float4(0.f, 0.f, 0.f, 0.f);
#pragma unroll
    for (int q = 0; q < 8; q++) {
        int4   iv = *(const int4*)(ip + q * 4);
        float4 wv = *(const float4*)(wp + q * 4);
        float4 v0 = *(const float4*)(g_Et + (size_t)iv.x * HDIM + c4);
        float4 v1 = *(const float4*)(g_Et + (size_t)iv.y * HDIM + c4);
        float4 v2 = *(const float4*)(g_Et + (size_t)iv.z * HDIM + c4);
        float4 v3 = *(const float4*)(g_Et + (size_t)iv.w * HDIM + c4);
        acc.x += v0.x*wv.x + v1.x*wv.y + v2.x*wv.z + v3.x*wv.w;
        acc.y += v0.y*wv.x + v1.y*wv.y + v2.y*wv.z + v3.y*wv.w;
        acc.z += v0.z*wv.x + v1.z*wv.y + v2.z*wv.z + v3.z*wv.w;
        acc.w += v0.w*wv.x + v1.w*wv.y + v2.w*wv.z + v3.w*wv.w;
    }
    if (n < L) {
        *(float4*)(g_node_h + (size_t)n * HDIM + c4) = acc;
    } else {
        const size_t pp = (size_t)(n - L) * HDIM + c4;
        uint32_t lo0, lo1;
        uint32_t h0 = pack2(acc.x, acc.y, &lo0);
        uint32_t h1 = pack2(acc.z, acc.w, &lo1);
        *(uint2*)&g_xeh[pp] = make_uint2(h0, h1);
        *(uint2*)&g_xel[pp] = make_uint2(lo0, lo1);
    }
}

// ---------------- the persistent kernel ----------------
extern "C" __global__ void __launch_bounds__(256, 2) star_all(
    const float* __restrict__ xw, const int* __restrict__ xi, const int* __restrict__ tree,
    const float* __restrict__ Ebu,
    const float* __restrict__ Wz, const float* __restrict__ Uz, const float* __restrict__ bz,
    const float* __restrict__ Wr, const float* __restrict__ Ur, const float* __restrict__ br,
    const float* __restrict__ Wh, const float* __restrict__ Uh, const float* __restrict__ bh,
    const float* __restrict__ Wout, const float* __restrict__ bout,
    float* __restrict__ out, int N, int P)
{
    extern __shared__ char smem[];
    const uint32_t sb = s2u(smem);

    const int L = N - P;
    const int tid = threadIdx.x;
    const int gtid = blockIdx.x * blockDim.x + tid;
    const int nthreads = gridDim.x * blockDim.x;

    // ---- P0: init + weight bf16 split + tiled transpose of E ----
    for (int n = gtid; n < N; n += nthreads) g_lvl[n] = (n < L) ? 0 : -1;
    for (int i = gtid; i < MAXLVL; i += nthreads) g_lvl_cnt[i] = 0;
    if (gtid == 0) g_maxlvl = 0;
    for (int e = gtid; e < 1536 * HDIM; e += nthreads) {
        int r = e >> 9, c = e & 511;
        float w = (r < 512) ? Wz[r * 512 + c] : (r < 1024) ? Wr[(r - 512) * 512 + c]
                                              : Wh[(r - 1024) * 512 + c];
        bsplit(w, &g_Wbh[e], &g_Wbl[e]);
    }
    for (int e = gtid; e < 1024 * HDIM; e += nthreads) {
        int r = e >> 9, c = e & 511;
        float w = (r < 512) ? Uz[r * 512 + c] : Ur[(r - 512) * 512 + c];
        bsplit(w, &g_Uzh[e], &g_Uzl[e]);
    }
    for (int e = gtid; e < 512 * HDIM; e += nthreads)
        bsplit(Uh[e], &g_Uhh[e], &g_Uhl[e]);
    for (int i = gtid; i < 1536; i += nthreads)
        g_bcat[i] = (i < 512) ? bz[i] : (i < 1024) ? br[i - 512] : bh[i - 1024];
    {
        float (*tp)[33] = (float(*)[33])smem;
        const int nvt = (VOCABC + 31) >> 5;
        const int nht = HDIM >> 5;
        const int tx = tid & 31, ty = tid >> 5;
        for (int t = blockIdx.x; t < nvt * nht; t += gridDim.x) {
            const int vt = t / nht, ht = t - vt * nht;
            const int v0 = vt << 5, h0 = ht << 5;
            __syncthreads();
#pragma unroll
            for (int i = 0; i < 4; i++) {
                int r = ty + i * 8;
                int v = v0 + tx;
                if (v < VOCABC) tp[r][tx] = Ebu[(size_t)(h0 + r) * VOCABC + v];
            }
            __syncthreads();
#pragma unroll
            for (int i = 0; i < 4; i++) {
                int r = ty + i * 8;
                int v = v0 + r;
                if (v < VOCABC) g_Et[(size_t)v * HDIM + h0 + tx] = tp[tx][r];
            }
        }
        __syncthreads();
    }
    gbar();

    // ---- P1: parent embedding + level discovery ----
    for (int n0 = L + blockIdx.x * 2; n0 < N; n0 += gridDim.x * 2)
        embed_pair(n0, L, N, xw, xi);
    for (int p = gtid; p < P; p += nthreads) {
        int lv = 0;
#pragma unroll
        for (int i = 0; i < 4; i++) {
            int c = tree[p * 4 + i];
            if (c >= 0) {
                int cl;
                if (c < L) cl = 0;
                else { while ((cl = *((volatile int*)&g_lvl[c])) < 0) { __nanosleep(32); } }
                lv = max(lv, cl);
            }
        }
        lv += 1;
        *((volatile int*)&g_lvl[L + p]) = lv;
        atomicAdd(&g_lvl_cnt[lv], 1);
        atomicMax(&g_maxlvl, lv);
    }
    gbar();

    // ---- P2: leaf embedding (blocks < E) || Wx GEMM (blocks >= E) ----
    {
        const int E = min(176, (int)gridDim.x * 4 / 7);
        if (blockIdx.x == 0 && tid == 0) {
            int ml = g_maxlvl;
            int run = 0;
            for (int lv = 1; lv <= ml; lv++) {
                g_lvl_off[lv] = run;
                g_lvl_cur[lv] = run;
                run += g_lvl_cnt[lv];
            }
            g_lvl_off[ml + 1] = run;
        }
        if ((int)blockIdx.x < E) {
            __syncthreads();
            for (int n0 = blockIdx.x * 2; n0 < L; n0 += E * 2)
                embed_pair(n0, L, L, xw, xi);
        } else {
            tgemm<0>(smem, sb, P, nullptr, g_xeh, g_xel, g_Wbh, g_Wbl,
                     1536, L, blockIdx.x - E, gridDim.x - E);
        }
    }
    gbar();

    // ---- P3: scatter parents into level order ----
    for (int p = gtid; p < P; p += nthreads) {
        int lv = g_lvl[L + p];
        int slot = atomicAdd(&g_lvl_cur[lv], 1);
        g_order[slot] = p;
    }
    gbar();

    // ---- level loop ----
    const int maxlvl = g_maxlvl;
    for (int lv = 1; lv <= maxlvl; lv++) {
        const int off = g_lvl_off[lv];
        const int cnt = g_lvl_off[lv + 1] - off;
        if (cnt == 0) continue;
        attn_phase(off, cnt, tree);
        gbar();
        tgemm<1>(smem, sb, cnt, g_order + off, g_memh, g_meml,
                 g_Uzh, g_Uzl, 1024, L, blockIdx.x, gridDim.x);
        gbar();
        tgemm<2>(smem, sb, cnt, g_order + off, g_mrh, g_mrl,
                 g_Uhh, g_Uhl, 512, L, blockIdx.x, gridDim.x);
        gbar();
    }

    // ---- P5: per-CTA column max over parents ----
    {
        const int rpc = (P + gridDim.x - 1) / gridDim.x;
        const int r0 = blockIdx.x * rpc;
        const int r1 = min(r0 + rpc, P);
        const int c0 = tid, c1 = tid + 256;
        float v0 = -3.4e38f, v1 = -3.4e38f;
        for (int r = r0; r < r1; r++) {
            const float* row = g_node_h + (size_t)(L + r) * HDIM;
            v0 = fmaxf(v0, row[c0]);
            v1 = fmaxf(v1, row[c1]);
        }
        g_part[(size_t)blockIdx.x * HDIM + c0] = v0;
        g_part[(size_t)blockIdx.x * HDIM + c1] = v1;
    }
    gbar();

    // ---- P6: block 0: reduce, matvec, softmax ----
    if (blockIdx.x == 0) {
        float* sfinal = (float*)smem;
        float* slog   = sfinal + HDIM;
        const int c0 = tid, c1 = tid + 256;
        float v0 = -3.4e38f, v1 = -3.4e38f;
        for (int g = 0; g < (int)gridDim.x; g++) {
            v0 = fmaxf(v0, g_part[(size_t)g * HDIM + c0]);
            v1 = fmaxf(v1, g_part[(size_t)g * HDIM + c1]);
        }
        sfinal[c0] = v0; sfinal[c1] = v1;
        __syncthreads();
        const int w = tid >> 5, lane = tid & 31;
        if (w < 4) {
            float t = 0.f;
#pragma unroll
            for (int j = 0; j < 16; j++) {
                int c = lane * 16 + j;
                t += Wout[w * HDIM + c] * sfinal[c];
            }
#pragma unroll
            for (int d = 16; d > 0; d >>= 1) t += __shfl_xor_sync(0xffffffffu, t, d);
            if (lane == 0) slog[w] = t + bout[w];
        }
        __syncthreads();
        if (tid == 0) {
            float mx = fmaxf(fmaxf(slog[0], slog[1]), fmaxf(slog[2], slog[3]));
            float e0 = __expf(slog[0]-mx), e1 = __expf(slog[1]-mx);
            float e2 = __expf(slog[2]-mx), e3 = __expf(slog[3]-mx);
            float inv = 1.f / (e0+e1+e2+e3);
            out[0] = e0*inv; out[1] = e1*inv; out[2] = e2*inv; out[3] = e3*inv;
        }
    }
}

extern "C" void kernel_launch(void* const* d_in, const int* in_sizes, int n_in,
                              void* d_out, int out_size) {
    const float* xw   = (const float*)d_in[0];
    const int*   xi   = (const int*)  d_in[1];
    const int*   tree = (const int*)  d_in[2];
    const float* Ebu  = (const float*)d_in[3];
    const float* Wz   = (const float*)d_in[4];
    const float* Uz   = (const float*)d_in[5];
    const float* bz   = (const float*)d_in[6];
    const float* Wr   = (const float*)d_in[7];
    const float* Ur   = (const float*)d_in[8];
    const float* br   = (const float*)d_in[9];
    const float* Wh   = (const float*)d_in[10];
    const float* Uh   = (const float*)d_in[11];
    const float* bh   = (const float*)d_in[12];
    const float* Wout = (const float*)d_in[13];
    const float* bout = (const float*)d_in[14];
    float* out = (float*)d_out;

    const int N = in_sizes[0] / LWN;
    const int P = in_sizes[2] / 4;

    int dev = 0;
    cudaGetDevice(&dev);
    int smCount = 148;
    cudaDeviceGetAttribute(&smCount, cudaDevAttrMultiProcessorCount, dev);

    cudaFuncSetAttribute(star_all, cudaFuncAttributeMaxDynamicSharedMemorySize, SMEM_REQ);
    int bpm = 1;
    cudaOccupancyMaxActiveBlocksPerMultiprocessor(&bpm, star_all, 256, SMEM_REQ);
    if (bpm < 1) bpm = 1;
    int grid = smCount * bpm;
    if (grid > MAXCTAS) grid = MAXCTAS;

    star_all<<<grid, 256, SMEM_REQ>>>(xw, xi, tree, Ebu, Wz, Uz, bz, Wr, Ur, br,
                                      Wh, Uh, bh, Wout, bout, out, N, P);
}